// round 14
// baseline (speedup 1.0000x reference)
#include <cuda_runtime.h>
#include <stdint.h>
#include <math.h>

#define NN 6144
#define NV 3
#define NK 10
#define NF 512
#define YP 12
#define NITERS 2
#define BN_EPS 1e-5f

#define MSPLIT 3
#define M_CHUNK 2048                   // m per tile (one fill)
#define MQP 516                        // 512 + pad (u64 row stride)
#define STEPS 16                       // 2048 / 128
#define ZSLICE (4 * 5 * MQP)           // 10320 u64 per m-slice (82,560 B)

#define GEMV_THREADS 384               // 12 warps -> reg cap 170
#define RPW 8
#define ROWS_PER_BLOCK 96              // 12 warps * 8 rows
#define NRT (NN / ROWS_PER_BLOCK)      // 64 row-tiles per view
#define NTILES (MSPLIT * NV * NRT)     // 576

// ---------------- scratch ----------------
__device__ float g_proj[NV * NN * YP];
__device__ float g_Y[MSPLIT * NV * NN * YP];   // m-split partials
__device__ float g_z[NN * YP];
__device__ __align__(16) unsigned long long g_zpack[MSPLIT][ZSLICE];
__device__ float g_stats[NITERS * 2 * NK];
__device__ int   g_cnt[NITERS];
__device__ int   g_tk[NITERS];

// ---------------- packed f32x2 helpers ----------------
__device__ __forceinline__ unsigned long long pack2(float a, float b) {
    unsigned long long r;
    asm("mov.b64 %0, {%1, %2};" : "=l"(r) : "f"(a), "f"(b));
    return r;
}
__device__ __forceinline__ void ffma2(unsigned long long& d, unsigned long long a, unsigned long long b) {
    asm("fma.rn.f32x2 %0, %1, %2, %0;" : "+l"(d) : "l"(a), "l"(b));
}
__device__ __forceinline__ void fadd2(unsigned long long& d, unsigned long long a) {
    asm("add.rn.f32x2 %0, %0, %1;" : "+l"(d) : "l"(a));
}
__device__ __forceinline__ float2 unpack2(unsigned long long v) {
    float2 r;
    asm("mov.b64 {%0, %1}, %2;" : "=f"(r.x), "=f"(r.y) : "l"(v));
    return r;
}
__device__ __forceinline__ void cp_async16(void* smem_dst, const void* gmem_src) {
    unsigned int s = (unsigned int)__cvta_generic_to_shared(smem_dst);
    asm volatile("cp.async.cg.shared.global [%0], [%1], 16;" :: "r"(s), "l"(gmem_src));
}

// zpack float index for (m, k)
__device__ __forceinline__ void zpack_store(int m, int k, float val) {
    int ms = m >> 11;
    int j = m & 2047;
    int idx = (((j & 3) * 5 + (k >> 1)) * MQP + (j >> 2)) * 2 + (k & 1);
    ((float*)g_zpack[ms])[idx] = val;
}

// ---------------- kernel 1: proj (+ zpack z0, zero stats/counters) ----------------
__global__ __launch_bounds__(256) void proj_kernel(const float* __restrict__ feat,
                                                   const float* __restrict__ U,
                                                   const float* __restrict__ z0) {
    __shared__ float Ut[NK][NF];
    int tid = threadIdx.x, lane = tid & 31, wid = tid >> 5;
    int bx = blockIdx.x;
    if (bx == 0) {
        if (tid < NITERS * 2 * NK) g_stats[tid] = 0.0f;
        if (tid >= 64 && tid < 64 + NITERS) g_cnt[tid - 64] = 0;
        if (tid >= 96 && tid < 96 + NITERS) g_tk[tid - 96] = 0;
    }
    if (bx < NN / 256) {
        int m = bx * 256 + tid;
#pragma unroll
        for (int k = 0; k < NK; k++) zpack_store(m, k, z0[(size_t)m * NK + k]);
    }

    int v = bx / (NN / 8);
    int rb = bx % (NN / 8);

    for (int i = tid; i < NF * NK; i += 256) {
        int f = i / NK, k = i % NK;
        Ut[k][f] = U[(size_t)v * NF * NK + i];
    }
    __syncthreads();

    int n = rb * 8 + wid;
    const float4* xr = (const float4*)(feat + ((size_t)v * NN + n) * NF);
    float acc[NK];
#pragma unroll
    for (int k = 0; k < NK; k++) acc[k] = 0.0f;

#pragma unroll
    for (int it = 0; it < NF / 128; it++) {
        int f4 = it * 32 + lane;
        float4 x = xr[f4];
#pragma unroll
        for (int k = 0; k < NK; k++) {
            float4 u = *(const float4*)&Ut[k][f4 * 4];
            acc[k] = fmaf(x.x, u.x, acc[k]);
            acc[k] = fmaf(x.y, u.y, acc[k]);
            acc[k] = fmaf(x.z, u.z, acc[k]);
            acc[k] = fmaf(x.w, u.w, acc[k]);
        }
    }
#pragma unroll
    for (int k = 0; k < NK; k++)
        for (int s = 16; s; s >>= 1) acc[k] += __shfl_xor_sync(0xffffffffu, acc[k], s);

    if (lane == 0) {
        float* pr = g_proj + ((size_t)v * NN + n) * YP;
#pragma unroll
        for (int k = 0; k < NK; k++) pr[k] = acc[k];
    }
}

// ---------------- kernel 2: persistent ticketed gemv ----------------
#define HALF_STEP(CONS, PRE, IT)                                                   \
    do {                                                                           \
        int it_ = (IT);                                                            \
        if (it_ + 1 < STEPS) {                                                     \
            _Pragma("unroll")                                                      \
            for (int r = 0; r < RPW; r++)                                          \
                PRE[r] = __ldcs(Lt + (size_t)r * ROW4 + (it_ + 1) * 32 + lane);    \
        }                                                                          \
        int mi_ = it_ * 32 + lane;                                                 \
        _Pragma("unroll")                                                          \
        for (int q = 0; q < 4; q++) {                                              \
            unsigned long long zq[5];                                              \
            _Pragma("unroll")                                                      \
            for (int p = 0; p < 5; p++) zq[p] = zt[(q * 5 + p) * MQP + mi_];       \
            _Pragma("unroll")                                                      \
            for (int r = 0; r < RPW; r++) {                                        \
                float av_ = (q == 0) ? CONS[r].x : (q == 1) ? CONS[r].y            \
                           : (q == 2) ? CONS[r].z : CONS[r].w;                     \
                unsigned long long d_ = pack2(av_, av_);                           \
                _Pragma("unroll")                                                  \
                for (int p = 0; p < 5; p++) ffma2(acc[r][p], d_, zq[p]);           \
            }                                                                      \
        }                                                                          \
    } while (0)

__device__ __forceinline__ void zfill(unsigned long long* zt, int ms, int tid) {
    const char* src = (const char*)g_zpack[ms];
    char* dst = (char*)zt;
#pragma unroll 1
    for (int i = tid; i < ZSLICE / 2; i += GEMV_THREADS)
        cp_async16(dst + (size_t)i * 16, src + (size_t)i * 16);
    asm volatile("cp.async.commit_group;");
}

__global__ __launch_bounds__(GEMV_THREADS) void gemv_kernel(const float* __restrict__ lap, int t) {
    extern __shared__ unsigned long long zt[];   // ZSLICE u64 = 82,560 B
    __shared__ int s_tile;

    int tid = threadIdx.x, lane = tid & 31, wid = tid >> 5;
    const int ROW4 = NN / 4;

    if (tid == 0) s_tile = atomicAdd(&g_tk[t], 1);
    __syncthreads();
    int tile = s_tile;
    if (tile >= NTILES) return;

    // initial fill + wait
    zfill(zt, tile / (NV * NRT), tid);

    int ms = tile / (NV * NRT);
    int rem = tile % (NV * NRT);
    const float4* Lt = (const float4*)(lap + ((size_t)(rem / NRT) * NN
                       + (size_t)(rem % NRT) * ROWS_PER_BLOCK + wid * RPW) * (size_t)NN)
                       + ms * (M_CHUNK / 4);

    float4 a[RPW], b[RPW];
    // prologue L loads overlap the fill
#pragma unroll
    for (int r = 0; r < RPW; r++) a[r] = __ldcs(Lt + (size_t)r * ROW4 + lane);
    asm volatile("cp.async.wait_group 0;");
    __syncthreads();

#pragma unroll 1
    while (true) {
        unsigned long long acc[RPW][5];
#pragma unroll
        for (int r = 0; r < RPW; r++)
#pragma unroll
            for (int p = 0; p < 5; p++) acc[r][p] = 0ull;

#pragma unroll 1
        for (int it2 = 0; it2 < STEPS / 2; it2++) {
            HALF_STEP(a, b, it2 * 2);
            HALF_STEP(b, a, it2 * 2 + 1);
        }

        // grab next tile; barrier doubles as "all warps done reading zt"
        if (tid == 0) s_tile = atomicAdd(&g_tk[t], 1);
        __syncthreads();
        int next = s_tile;

        const float4* Lt_next = Lt;
        if (next < NTILES) {
            int nms = next / (NV * NRT);
            int nrem = next % (NV * NRT);
            zfill(zt, nms, tid);
            Lt_next = (const float4*)(lap + ((size_t)(nrem / NRT) * NN
                       + (size_t)(nrem % NRT) * ROWS_PER_BLOCK + wid * RPW) * (size_t)NN)
                       + nms * (M_CHUNK / 4);
            // next tile's prologue L loads, overlapped with epilogue below
#pragma unroll
            for (int r = 0; r < RPW; r++) a[r] = __ldcs(Lt_next + (size_t)r * ROW4 + lane);
        }

        // epilogue for current tile (registers + STG only)
        {
            int cms = tile / (NV * NRT);
            int crem = tile % (NV * NRT);
            int cv = crem / NRT;
            int cn0 = (crem % NRT) * ROWS_PER_BLOCK + wid * RPW;
#pragma unroll
            for (int r = 0; r < RPW; r++) {
#pragma unroll
                for (int p = 0; p < 5; p++) {
                    unsigned long long vv = acc[r][p];
#pragma unroll
                    for (int s = 16; s; s >>= 1) {
                        unsigned long long o = __shfl_xor_sync(0xffffffffu, vv, s);
                        fadd2(vv, o);
                    }
                    acc[r][p] = vv;
                }
                if (lane == 0) {
                    float* yr = g_Y + (((size_t)cms * NV + cv) * NN + cn0 + r) * YP;
#pragma unroll
                    for (int p = 0; p < 5; p++) {
                        float2 f = unpack2(acc[r][p]);
                        yr[2 * p] = f.x;
                        yr[2 * p + 1] = f.y;
                    }
                }
            }
        }

        if (next >= NTILES) break;
        asm volatile("cp.async.wait_group 0;");
        __syncthreads();
        tile = next;
        Lt = Lt_next;
    }
}

// ---------------- kernel 3: fused combine + BN + SELU (+ zpack for next iter) ----------------
__device__ __forceinline__ float softplusf(float x) {
    return fmaxf(x, 0.0f) + __logf(1.0f + __expf(-fabsf(x)));
}

__device__ __forceinline__ void ds_comb(float* a1, const float* a2) {
    float S1 = 0.0f, S2 = 0.0f;
#pragma unroll
    for (int k = 0; k < NK; k++) { S1 += a1[k]; S2 += a2[k]; }
    float i1 = 1.0f / S1, i2 = 1.0f / S2;
    float u1 = (float)NK * i1, u2 = (float)NK * i2;
    float b1[NK], b2[NK];
    float sb1 = 0.0f, sb2 = 0.0f, dot = 0.0f;
#pragma unroll
    for (int k = 0; k < NK; k++) {
        b1[k] = (a1[k] - 1.0f) * i1;
        b2[k] = (a2[k] - 1.0f) * i2;
        sb1 += b1[k];
        sb2 += b2[k];
        dot += b1[k] * b2[k];
    }
    float C = sb1 * sb2 - dot;
    float invd = 1.0f / (1.0f - C);
    float Sn = (float)NK * (1.0f - C) / (u1 * u2);
#pragma unroll
    for (int k = 0; k < NK; k++)
        a1[k] = (b1[k] * b2[k] + b1[k] * u2 + b2[k] * u1) * invd * Sn + 1.0f;
}

__device__ __forceinline__ float seluf(float x) {
    const float sc = 1.0507009873554805f, al = 1.6732632423543772f;
    return x > 0.0f ? sc * x : sc * al * (__expf(x) - 1.0f);
}

#define CMB_THREADS 64
#define CMB_BLOCKS (NN / CMB_THREADS)   // 96 <= 148 -> co-resident, spin safe
__global__ __launch_bounds__(CMB_THREADS) void combine_bn_kernel(const float* __restrict__ z_ext,
                                                                 int use_ext, int t, int last,
                                                                 float* __restrict__ out,
                                                                 const float* __restrict__ gamma,
                                                                 const float* __restrict__ beta,
                                                                 const float* __restrict__ theta) {
    const float* zsrc = use_ext ? z_ext : g_z;
    const int zstr = use_ext ? NK : YP;
    int n = blockIdx.x * CMB_THREADS + threadIdx.x;
    int lane = threadIdx.x & 31;

    float zn[NK];
#pragma unroll
    for (int p = 0; p < 5; p++) {
        float2 zv = *(const float2*)(zsrc + (size_t)n * zstr + 2 * p);
        zn[2 * p] = zv.x;
        zn[2 * p + 1] = zv.y;
    }

    float ac[NK];
#pragma unroll
    for (int v = 0; v < NV; v++) {
        float yv[12], pv[12];
        const float4* p4 = (const float4*)(g_proj + ((size_t)v * NN + n) * YP);
#pragma unroll
        for (int q = 0; q < 3; q++) {
            float4 pq = p4[q];
            pv[4 * q] = pq.x; pv[4 * q + 1] = pq.y; pv[4 * q + 2] = pq.z; pv[4 * q + 3] = pq.w;
            yv[4 * q] = 0.0f; yv[4 * q + 1] = 0.0f; yv[4 * q + 2] = 0.0f; yv[4 * q + 3] = 0.0f;
        }
#pragma unroll
        for (int s = 0; s < MSPLIT; s++) {
            const float4* y4 = (const float4*)(g_Y + (((size_t)s * NV + v) * NN + n) * YP);
#pragma unroll
            for (int q = 0; q < 3; q++) {
                float4 yq = y4[q];
                yv[4 * q] += yq.x; yv[4 * q + 1] += yq.y; yv[4 * q + 2] += yq.z; yv[4 * q + 3] += yq.w;
            }
        }
        float av[NK];
#pragma unroll
        for (int k = 0; k < NK; k++) av[k] = softplusf(zn[k] - yv[k] + pv[k]) + 1.0f;
        if (v == 0) {
#pragma unroll
            for (int k = 0; k < NK; k++) ac[k] = av[k];
        } else {
            ds_comb(ac, av);
        }
    }

    float rs[NK], rq[NK];
#pragma unroll
    for (int k = 0; k < NK; k++) { rs[k] = ac[k]; rq[k] = ac[k] * ac[k]; }
#pragma unroll
    for (int k = 0; k < NK; k++) {
        for (int s = 16; s; s >>= 1) {
            rs[k] += __shfl_xor_sync(0xffffffffu, rs[k], s);
            rq[k] += __shfl_xor_sync(0xffffffffu, rq[k], s);
        }
    }
    __shared__ float sh[2 * NK];
    if (threadIdx.x < 2 * NK) sh[threadIdx.x] = 0.0f;
    __syncthreads();
    if (lane == 0) {
#pragma unroll
        for (int k = 0; k < NK; k++) {
            atomicAdd(&sh[k], rs[k]);
            atomicAdd(&sh[NK + k], rq[k]);
        }
    }
    __syncthreads();
    if (threadIdx.x < 2 * NK)
        atomicAdd(&g_stats[t * 2 * NK + threadIdx.x], sh[threadIdx.x]);

    __threadfence();
    __syncthreads();
    if (threadIdx.x == 0) {
        atomicAdd(&g_cnt[t], 1);
        while (atomicAdd(&g_cnt[t], 0) < CMB_BLOCKS) { __nanosleep(64); }
    }
    __syncthreads();
    __threadfence();

    float th = theta[0];
#pragma unroll
    for (int k = 0; k < NK; k++) {
        float mu = g_stats[t * 2 * NK + k] * (1.0f / NN);
        float ms = g_stats[t * 2 * NK + NK + k] * (1.0f / NN);
        float var = ms - mu * mu;
        float inv = rsqrtf(var + BN_EPS);
        float hn = (ac[k] - mu) * inv * gamma[k] + beta[k];
        float zz = seluf(hn - th) - seluf(-hn - th);
        out[(size_t)t * NN * NK + (size_t)n * NK + k] = zz;
        if (!last) {
            g_z[(size_t)n * YP + k] = zz;
            zpack_store(n, k, zz);
        }
    }
}

// ---------------- launcher ----------------
extern "C" void kernel_launch(void* const* d_in, const int* in_sizes, int n_in,
                              void* d_out, int out_size) {
    (void)in_sizes; (void)n_in; (void)out_size;
    const float* feat  = (const float*)d_in[0];
    const float* lap   = (const float*)d_in[1];
    const float* z0    = (const float*)d_in[2];
    const float* U     = (const float*)d_in[3];
    const float* theta = (const float*)d_in[4];
    const float* gamma = (const float*)d_in[5];
    const float* beta  = (const float*)d_in[6];
    float* out = (float*)d_out;

    const int ZT_BYTES = ZSLICE * 8;   // 82,560 B dynamic smem
    static int nsm = 0;
    if (nsm == 0) {
        cudaFuncSetAttribute(gemv_kernel, cudaFuncAttributeMaxDynamicSharedMemorySize, ZT_BYTES);
        cudaDeviceGetAttribute(&nsm, cudaDevAttrMultiProcessorCount, 0);
        if (nsm <= 0) nsm = 148;
        if (nsm > NTILES) nsm = NTILES;
    }

    proj_kernel<<<NV * (NN / 8), 256>>>(feat, U, z0);

    for (int t = 0; t < NITERS; t++) {
        int use_ext = (t == 0) ? 1 : 0;
        gemv_kernel<<<nsm, GEMV_THREADS, ZT_BYTES>>>(lap, t);
        combine_bn_kernel<<<CMB_BLOCKS, CMB_THREADS>>>(z0, use_ext, t, t == NITERS - 1,
                                                       out, gamma, beta, theta);
    }
}

// round 15
// speedup vs baseline: 1.0503x; 1.0503x over previous
#include <cuda_runtime.h>
#include <stdint.h>
#include <math.h>

#define NN 6144
#define NV 3
#define NK 10
#define NF 512
#define YP 12
#define NITERS 2
#define BN_EPS 1e-5f

#define MSPLIT 3
#define M_CHUNK 2048                   // m per tile (one fill)
#define MQP 516                        // 512 + pad (u64 row stride)
#define STEPS 16                       // 2048 / 128
#define ZSLICE (4 * 5 * MQP)           // 10320 u64 per m-slice (82,560 B)

#define GEMV_THREADS 384               // 12 warps -> reg cap ~170
#define RPW 8
#define ROWS_PER_BLOCK 96              // 12 warps * 8 rows
#define NRT (NN / ROWS_PER_BLOCK)      // 64 row-tiles per view
#define NTILES (MSPLIT * NV * NRT)     // 576
#define PROJ_RPB 12                    // proj rows per block (1/warp)
#define PROJ_BLOCKS (NV * (NN / PROJ_RPB))   // 1536

// ---------------- scratch ----------------
__device__ float g_proj[NV * NN * YP];
__device__ float g_Y[MSPLIT * NV * NN * YP];   // m-split partials
__device__ float g_z[NN * YP];
__device__ __align__(16) unsigned long long g_zpack[MSPLIT][ZSLICE];
__device__ float g_stats[NITERS * 2 * NK];
__device__ int   g_cnt[NITERS];

// ---------------- packed f32x2 helpers ----------------
__device__ __forceinline__ unsigned long long pack2(float a, float b) {
    unsigned long long r;
    asm("mov.b64 %0, {%1, %2};" : "=l"(r) : "f"(a), "f"(b));
    return r;
}
__device__ __forceinline__ void ffma2(unsigned long long& d, unsigned long long a, unsigned long long b) {
    asm("fma.rn.f32x2 %0, %1, %2, %0;" : "+l"(d) : "l"(a), "l"(b));
}
__device__ __forceinline__ void fadd2(unsigned long long& d, unsigned long long a) {
    asm("add.rn.f32x2 %0, %0, %1;" : "+l"(d) : "l"(a));
}
__device__ __forceinline__ float2 unpack2(unsigned long long v) {
    float2 r;
    asm("mov.b64 {%0, %1}, %2;" : "=f"(r.x), "=f"(r.y) : "l"(v));
    return r;
}
__device__ __forceinline__ void cp_async16(void* smem_dst, const void* gmem_src) {
    unsigned int s = (unsigned int)__cvta_generic_to_shared(smem_dst);
    asm volatile("cp.async.cg.shared.global [%0], [%1], 16;" :: "r"(s), "l"(gmem_src));
}

// zpack float index for (m, k)
__device__ __forceinline__ void zpack_store(int m, int k, float val) {
    int ms = m >> 11;
    int j = m & 2047;
    int idx = (((j & 3) * 5 + (k >> 1)) * MQP + (j >> 2)) * 2 + (k & 1);
    ((float*)g_zpack[ms])[idx] = val;
}

// ---------------- kernel: gemv tiles + (t=0 only) fused proj blocks ----------------
#define HALF_STEP(CONS, PRE, IT)                                                   \
    do {                                                                           \
        int it_ = (IT);                                                            \
        if (it_ + 1 < STEPS) {                                                     \
            _Pragma("unroll")                                                      \
            for (int r = 0; r < RPW; r++)                                          \
                PRE[r] = __ldcs(Lt + (size_t)r * ROW4 + (it_ + 1) * 32 + lane);    \
        }                                                                          \
        int mi_ = it_ * 32 + lane;                                                 \
        _Pragma("unroll")                                                          \
        for (int q = 0; q < 4; q++) {                                              \
            unsigned long long zq[5];                                              \
            _Pragma("unroll")                                                      \
            for (int p = 0; p < 5; p++) zq[p] = zt[(q * 5 + p) * MQP + mi_];       \
            _Pragma("unroll")                                                      \
            for (int r = 0; r < RPW; r++) {                                        \
                float av_ = (q == 0) ? CONS[r].x : (q == 1) ? CONS[r].y            \
                           : (q == 2) ? CONS[r].z : CONS[r].w;                     \
                unsigned long long d_ = pack2(av_, av_);                           \
                _Pragma("unroll")                                                  \
                for (int p = 0; p < 5; p++) ffma2(acc[r][p], d_, zq[p]);           \
            }                                                                      \
        }                                                                          \
    } while (0)

__global__ __launch_bounds__(GEMV_THREADS) void gemv_kernel(const float* __restrict__ lap,
                                                            const float* __restrict__ z_ext,
                                                            int use_ext,
                                                            const float* __restrict__ feat,
                                                            const float* __restrict__ U) {
    extern __shared__ unsigned long long zt[];   // ZSLICE u64 = 82,560 B
    int tid = threadIdx.x, lane = tid & 31, wid = tid >> 5;
    int bx = blockIdx.x;

    if (bx >= NTILES) {
        // ---------------- fused proj path (t=0 launch only) ----------------
        int pb = bx - NTILES;
        if (pb == 0) {
            if (tid < NITERS * 2 * NK) g_stats[tid] = 0.0f;
            if (tid >= 64 && tid < 64 + NITERS) g_cnt[tid - 64] = 0;
        }
        float (*Ut)[NF] = (float (*)[NF])zt;   // 20 KB alias of dynamic smem
        int v = pb / (NN / PROJ_RPB);
        int rb = pb % (NN / PROJ_RPB);

        for (int i = tid; i < NF * NK; i += GEMV_THREADS) {
            int f = i / NK, k = i % NK;
            Ut[k][f] = U[(size_t)v * NF * NK + i];
        }
        __syncthreads();

        int n = rb * PROJ_RPB + wid;
        const float4* xr = (const float4*)(feat + ((size_t)v * NN + n) * NF);
        float acc[NK];
#pragma unroll
        for (int k = 0; k < NK; k++) acc[k] = 0.0f;
#pragma unroll
        for (int it = 0; it < NF / 128; it++) {
            int f4 = it * 32 + lane;
            float4 x = xr[f4];
#pragma unroll
            for (int k = 0; k < NK; k++) {
                float4 u = *(const float4*)&Ut[k][f4 * 4];
                acc[k] = fmaf(x.x, u.x, acc[k]);
                acc[k] = fmaf(x.y, u.y, acc[k]);
                acc[k] = fmaf(x.z, u.z, acc[k]);
                acc[k] = fmaf(x.w, u.w, acc[k]);
            }
        }
#pragma unroll
        for (int k = 0; k < NK; k++)
            for (int s = 16; s; s >>= 1) acc[k] += __shfl_xor_sync(0xffffffffu, acc[k], s);
        if (lane == 0) {
            float* pr = g_proj + ((size_t)v * NN + n) * YP;
#pragma unroll
            for (int k = 0; k < NK; k++) pr[k] = acc[k];
        }
        return;
    }

    // ---------------- gemv tile path ----------------
    int ms = bx / (NV * NRT);
    int rem = bx % (NV * NRT);
    int v = rem / NRT;
    int rt = rem % NRT;
    int n0 = rt * ROWS_PER_BLOCK + wid * RPW;

    const int ROW4 = NN / 4;
    const float4* Lt = (const float4*)(lap + ((size_t)v * NN + n0) * (size_t)NN) + ms * (M_CHUNK / 4);

    // z fill
    if (use_ext) {
        // pack directly from z0 [m][NK] (sync)
        for (int i = tid; i < 5 * M_CHUNK; i += GEMV_THREADS) {
            int p = i >> 11;
            int j = i & (M_CHUNK - 1);
            const float2* zp2 = (const float2*)(z_ext + (size_t)(ms * M_CHUNK + j) * NK + 2 * p);
            float2 zv = *zp2;
            zt[((j & 3) * 5 + p) * MQP + (j >> 2)] = pack2(zv.x, zv.y);
        }
    } else {
        // contiguous cp.async copy from pre-packed global
        const char* src = (const char*)g_zpack[ms];
        char* dst = (char*)zt;
#pragma unroll 1
        for (int i = tid; i < ZSLICE / 2; i += GEMV_THREADS)
            cp_async16(dst + (size_t)i * 16, src + (size_t)i * 16);
        asm volatile("cp.async.commit_group;");
    }

    unsigned long long acc[RPW][5];
#pragma unroll
    for (int r = 0; r < RPW; r++)
#pragma unroll
        for (int p = 0; p < 5; p++) acc[r][p] = 0ull;

    float4 a[RPW], b[RPW];
#pragma unroll
    for (int r = 0; r < RPW; r++) a[r] = __ldcs(Lt + (size_t)r * ROW4 + lane);

    if (!use_ext) asm volatile("cp.async.wait_group 0;");
    __syncthreads();

#pragma unroll 1
    for (int it2 = 0; it2 < STEPS / 2; it2++) {
        HALF_STEP(a, b, it2 * 2);
        HALF_STEP(b, a, it2 * 2 + 1);
    }

    // epilogue: packed butterfly reduce, lane 0 stores Y partial
#pragma unroll
    for (int r = 0; r < RPW; r++) {
#pragma unroll
        for (int p = 0; p < 5; p++) {
            unsigned long long vv = acc[r][p];
#pragma unroll
            for (int s = 16; s; s >>= 1) {
                unsigned long long o = __shfl_xor_sync(0xffffffffu, vv, s);
                fadd2(vv, o);
            }
            acc[r][p] = vv;
        }
        if (lane == 0) {
            float* yr = g_Y + (((size_t)ms * NV + v) * NN + n0 + r) * YP;
#pragma unroll
            for (int p = 0; p < 5; p++) {
                float2 f = unpack2(acc[r][p]);
                yr[2 * p] = f.x;
                yr[2 * p + 1] = f.y;
            }
        }
    }
}

// ---------------- kernel: fused combine + BN + SELU (+ zpack for next iter) ----------------
__device__ __forceinline__ float softplusf(float x) {
    return fmaxf(x, 0.0f) + __logf(1.0f + __expf(-fabsf(x)));
}

__device__ __forceinline__ void ds_comb(float* a1, const float* a2) {
    float S1 = 0.0f, S2 = 0.0f;
#pragma unroll
    for (int k = 0; k < NK; k++) { S1 += a1[k]; S2 += a2[k]; }
    float i1 = 1.0f / S1, i2 = 1.0f / S2;
    float u1 = (float)NK * i1, u2 = (float)NK * i2;
    float b1[NK], b2[NK];
    float sb1 = 0.0f, sb2 = 0.0f, dot = 0.0f;
#pragma unroll
    for (int k = 0; k < NK; k++) {
        b1[k] = (a1[k] - 1.0f) * i1;
        b2[k] = (a2[k] - 1.0f) * i2;
        sb1 += b1[k];
        sb2 += b2[k];
        dot += b1[k] * b2[k];
    }
    float C = sb1 * sb2 - dot;
    float invd = 1.0f / (1.0f - C);
    float Sn = (float)NK * (1.0f - C) / (u1 * u2);
#pragma unroll
    for (int k = 0; k < NK; k++)
        a1[k] = (b1[k] * b2[k] + b1[k] * u2 + b2[k] * u1) * invd * Sn + 1.0f;
}

__device__ __forceinline__ float seluf(float x) {
    const float sc = 1.0507009873554805f, al = 1.6732632423543772f;
    return x > 0.0f ? sc * x : sc * al * (__expf(x) - 1.0f);
}

#define CMB_THREADS 64
#define CMB_BLOCKS (NN / CMB_THREADS)   // 96 <= 148 -> co-resident, spin safe
__global__ __launch_bounds__(CMB_THREADS) void combine_bn_kernel(const float* __restrict__ z_ext,
                                                                 int use_ext, int t, int last,
                                                                 float* __restrict__ out,
                                                                 const float* __restrict__ gamma,
                                                                 const float* __restrict__ beta,
                                                                 const float* __restrict__ theta) {
    const float* zsrc = use_ext ? z_ext : g_z;
    const int zstr = use_ext ? NK : YP;
    int n = blockIdx.x * CMB_THREADS + threadIdx.x;
    int lane = threadIdx.x & 31;

    float zn[NK];
#pragma unroll
    for (int p = 0; p < 5; p++) {
        float2 zv = *(const float2*)(zsrc + (size_t)n * zstr + 2 * p);
        zn[2 * p] = zv.x;
        zn[2 * p + 1] = zv.y;
    }

    float ac[NK];
#pragma unroll
    for (int v = 0; v < NV; v++) {
        float yv[12], pv[12];
        const float4* p4 = (const float4*)(g_proj + ((size_t)v * NN + n) * YP);
#pragma unroll
        for (int q = 0; q < 3; q++) {
            float4 pq = p4[q];
            pv[4 * q] = pq.x; pv[4 * q + 1] = pq.y; pv[4 * q + 2] = pq.z; pv[4 * q + 3] = pq.w;
            yv[4 * q] = 0.0f; yv[4 * q + 1] = 0.0f; yv[4 * q + 2] = 0.0f; yv[4 * q + 3] = 0.0f;
        }
#pragma unroll
        for (int s = 0; s < MSPLIT; s++) {
            const float4* y4 = (const float4*)(g_Y + (((size_t)s * NV + v) * NN + n) * YP);
#pragma unroll
            for (int q = 0; q < 3; q++) {
                float4 yq = y4[q];
                yv[4 * q] += yq.x; yv[4 * q + 1] += yq.y; yv[4 * q + 2] += yq.z; yv[4 * q + 3] += yq.w;
            }
        }
        float av[NK];
#pragma unroll
        for (int k = 0; k < NK; k++) av[k] = softplusf(zn[k] - yv[k] + pv[k]) + 1.0f;
        if (v == 0) {
#pragma unroll
            for (int k = 0; k < NK; k++) ac[k] = av[k];
        } else {
            ds_comb(ac, av);
        }
    }

    float rs[NK], rq[NK];
#pragma unroll
    for (int k = 0; k < NK; k++) { rs[k] = ac[k]; rq[k] = ac[k] * ac[k]; }
#pragma unroll
    for (int k = 0; k < NK; k++) {
        for (int s = 16; s; s >>= 1) {
            rs[k] += __shfl_xor_sync(0xffffffffu, rs[k], s);
            rq[k] += __shfl_xor_sync(0xffffffffu, rq[k], s);
        }
    }
    __shared__ float sh[2 * NK];
    if (threadIdx.x < 2 * NK) sh[threadIdx.x] = 0.0f;
    __syncthreads();
    if (lane == 0) {
#pragma unroll
        for (int k = 0; k < NK; k++) {
            atomicAdd(&sh[k], rs[k]);
            atomicAdd(&sh[NK + k], rq[k]);
        }
    }
    __syncthreads();
    if (threadIdx.x < 2 * NK)
        atomicAdd(&g_stats[t * 2 * NK + threadIdx.x], sh[threadIdx.x]);

    __threadfence();
    __syncthreads();
    if (threadIdx.x == 0) {
        atomicAdd(&g_cnt[t], 1);
        while (atomicAdd(&g_cnt[t], 0) < CMB_BLOCKS) { __nanosleep(64); }
    }
    __syncthreads();
    __threadfence();

    float th = theta[0];
#pragma unroll
    for (int k = 0; k < NK; k++) {
        float mu = g_stats[t * 2 * NK + k] * (1.0f / NN);
        float ms = g_stats[t * 2 * NK + NK + k] * (1.0f / NN);
        float var = ms - mu * mu;
        float inv = rsqrtf(var + BN_EPS);
        float hn = (ac[k] - mu) * inv * gamma[k] + beta[k];
        float zz = seluf(hn - th) - seluf(-hn - th);
        out[(size_t)t * NN * NK + (size_t)n * NK + k] = zz;
        if (!last) {
            g_z[(size_t)n * YP + k] = zz;
            zpack_store(n, k, zz);
        }
    }
}

// ---------------- launcher ----------------
extern "C" void kernel_launch(void* const* d_in, const int* in_sizes, int n_in,
                              void* d_out, int out_size) {
    (void)in_sizes; (void)n_in; (void)out_size;
    const float* feat  = (const float*)d_in[0];
    const float* lap   = (const float*)d_in[1];
    const float* z0    = (const float*)d_in[2];
    const float* U     = (const float*)d_in[3];
    const float* theta = (const float*)d_in[4];
    const float* gamma = (const float*)d_in[5];
    const float* beta  = (const float*)d_in[6];
    float* out = (float*)d_out;

    const int ZT_BYTES = ZSLICE * 8;   // 82,560 B dynamic smem
    static int configured = 0;
    if (!configured) {
        cudaFuncSetAttribute(gemv_kernel, cudaFuncAttributeMaxDynamicSharedMemorySize, ZT_BYTES);
        configured = 1;
    }

    for (int t = 0; t < NITERS; t++) {
        int use_ext = (t == 0) ? 1 : 0;
        int grid = (t == 0) ? (NTILES + PROJ_BLOCKS) : NTILES;   // proj fused into t=0 wave
        gemv_kernel<<<grid, GEMV_THREADS, ZT_BYTES>>>(lap, z0, use_ext, feat, U);
        combine_bn_kernel<<<CMB_BLOCKS, CMB_THREADS>>>(z0, use_ext, t, t == NITERS - 1,
                                                       out, gamma, beta, theta);
    }
}